// round 10
// baseline (speedup 1.0000x reference)
#include <cuda_runtime.h>
#include <cuda_bf16.h>
#include <math.h>

// out[b,t,f,c] = sum_{s<=t} w^{t-s} x[b,s,f] + mem[b,f,c] * w^{t+1},
// w = exp(clip(a[f]) + i*b[c]) ==> complex IIR y[t] = w*y[t-1] + x[t], y[-1]=mem.
// Warp-local: warp = one f; lanes = (cpair, chunk0..15); chunk = 32 steps.
// Carry via Kogge-Stone weighted shuffle scan (weights = W32^(2^d) by squaring).
// Single __syncthreads (x staging) -> store stream overlaps compute across warps.

#define B_DIM 8
#define T_DIM 512
#define F_DIM 1024
#define C_DIM 4
#define LIMIT_F 0.0766433975f                 // log(F32_MAX)/1024 - 0.01
#define N_OUT   (B_DIM * T_DIM * F_DIM * C_DIM)
#define L_CHUNK 32
#define FT      8                             // f-values per block (= warps/block)
#define NTHR    256

typedef unsigned long long u64;

__device__ __forceinline__ u64 pack2(float lo, float hi) {
    u64 r; asm("mov.b64 %0, {%1, %2};" : "=l"(r) : "f"(lo), "f"(hi)); return r;
}
__device__ __forceinline__ void unpack2(u64 v, float& lo, float& hi) {
    asm("mov.b64 {%0, %1}, %2;" : "=f"(lo), "=f"(hi) : "l"(v));
}
__device__ __forceinline__ u64 fma2(u64 a, u64 b, u64 c) {
    u64 d; asm("fma.rn.f32x2 %0, %1, %2, %3;" : "=l"(d) : "l"(a), "l"(b), "l"(c)); return d;
}
__device__ __forceinline__ u64 mul2(u64 a, u64 b) {
    u64 d; asm("mul.rn.f32x2 %0, %1, %2;" : "=l"(d) : "l"(a), "l"(b)); return d;
}
__device__ __forceinline__ u64 add2(u64 a, u64 b) {
    u64 d; asm("add.rn.f32x2 %0, %1, %2;" : "=l"(d) : "l"(a), "l"(b)); return d;
}
__device__ __forceinline__ u64 neg2(u64 v) { return v ^ 0x8000000080000000ULL; }

// smem x layout: row t at t*8 + (t>>5)*4.  Skew = 4 floats per 32-row chunk
// group: keeps every row 16B-aligned (float4 staging legal) while spreading
// the 16 chunk groups over 8 banks (2-way LDS conflict, best possible under
// 16B alignment).
__device__ __forceinline__ int xrow(int t) { return t * FT + (t >> 5) * 4; }

__global__ __launch_bounds__(NTHR, 7)
void outer_laplace_ws(const float* __restrict__ x,
                      const float* __restrict__ mem_r,
                      const float* __restrict__ mem_i,
                      const float* __restrict__ a,
                      const float* __restrict__ b,
                      float* __restrict__ out,
                      int mode, long long cap_f2)
{
    __shared__ float xs[T_DIM * FT + 16 * 4];        // 4160 floats = 16.25 KB

    const int tid  = threadIdx.x;
    const int wid  = tid >> 5;                       // warp = f index in block
    const int lane = tid & 31;
    const int cp   = lane >> 4;                      // c{0,1} / c{2,3}
    const int lg   = lane & 15;                      // chunk 0..15
    const int c0   = cp << 1;

    const int bb = blockIdx.x >> 7;                  // batch
    const int f0 = (blockIdx.x & 127) * FT;
    const int f  = f0 + wid;

    // ---- stage x[b, :, f0:f0+8] into smem (skewed rows) ----
    const float4* xg = (const float4*)(x + (size_t)bb * T_DIM * F_DIM + f0);
    #pragma unroll 4
    for (int i = tid; i < T_DIM * 2; i += NTHR) {    // 1024 float4
        int t = i >> 1, q = i & 1;
        *(float4*)&xs[xrow(t) + q * 4] = xg[(size_t)t * (F_DIM / 4) + q];
    }

    // ---- step coefficient w (packed over channel pair) ----
    const float ac = fminf(fmaxf(a[f], -LIMIT_F), -1e-8f);
    const float er = expf(ac);
    const float b0 = b[c0], b1 = b[c0 + 1];
    float s0, cz0, s1, cz1;
    sincosf(b0, &s0, &cz0);  sincosf(b1, &s1, &cz1);
    const u64 Wr  = pack2(er * cz0,  er * cz1);
    const u64 Wi  = pack2(er * s0,   er * s1);
    const u64 Wni = neg2(Wi);

    __syncthreads();                                 // the ONLY block barrier

    // ---- phase 1: chunk-local scan from zero ----
    const float* xp = &xs[xrow(lg * L_CHUNK) + wid]; // same skew within chunk
    u64 sr = 0ull, si = 0ull;
    #pragma unroll 8
    for (int k = 0; k < L_CHUNK; ++k) {
        float xv = xp[k * FT];
        u64 xx = pack2(xv, xv);
        u64 nsr = fma2(Wr, sr, fma2(Wni, si, xx));
        u64 nsi = fma2(Wr, si, mul2(Wi, sr));
        sr = nsr;  si = nsi;
    }

    // ---- warp scan: inclusive weighted scan over 16-lane chunk groups ----
    const unsigned FULL = 0xFFFFFFFFu;
    {
        float eL = expf(ac * (float)L_CHUNK);
        float sL0, cL0, sL1, cL1;
        sincosf(b0 * (float)L_CHUNK, &sL0, &cL0);
        sincosf(b1 * (float)L_CHUNK, &sL1, &cL1);
        u64 WDr = pack2(eL * cL0, eL * cL1);         // W32^(2^d), squared per level
        u64 WDi = pack2(eL * sL0, eL * sL1);
        u64 ar = pack2(1.f, 1.f), ai = 0ull;         // accumulates w^(32*lg)

        #pragma unroll
        for (int d = 1; d < 16; d <<= 1) {
            u64 WDni = neg2(WDi);
            u64 pr = __shfl_up_sync(FULL, sr, d, 16);
            u64 pi = __shfl_up_sync(FULL, si, d, 16);
            if (lg >= d) {
                u64 nsr = fma2(WDr, pr, fma2(WDni, pi, sr));
                u64 nsi = fma2(WDr, pi, fma2(WDi, pr, si));
                sr = nsr;  si = nsi;
            }
            if (lg & d) {
                u64 nar = fma2(WDr, ar, mul2(WDni, ai));
                u64 nai = fma2(WDr, ai, mul2(WDi, ar));
                ar = nar;  ai = nai;
            }
            u64 nWr = fma2(WDr, WDr, mul2(WDni, WDi));   // WD <- WD^2
            u64 t2  = mul2(WDr, WDi);
            u64 nWi = add2(t2, t2);
            WDr = nWr;  WDi = nWi;
        }

        u64 exr = __shfl_up_sync(FULL, sr, 1, 16);   // exclusive prefix
        u64 exi = __shfl_up_sync(FULL, si, 1, 16);
        if (lg == 0) { exr = 0ull; exi = 0ull; }

        const int mbase = (((bb << 10) + f) << 2) + c0;
        u64 mr = pack2(mem_r[mbase], mem_r[mbase + 1]);
        u64 mi = pack2(mem_i[mbase], mem_i[mbase + 1]);
        u64 ani = neg2(ai);
        sr = fma2(ar, mr, fma2(ani, mi, exr));       // carry = w^(32lg)*mem + ex
        si = fma2(ar, mi, fma2(ai, mr, exi));
    }
    u64 ur = sr, ui = si;

    // ---- phase 2: re-scan with correct init, vector stores ----
    long long bidx = ((long long)bb * T_DIM + lg * L_CHUNK) * (F_DIM * C_DIM)
                   + (f << 2) + c0;                  // complex-element index

    if (mode == 0) {                                 // interleaved complex64
        float4* ow = (float4*)((float2*)out + bidx);
        const long long stride4 = (long long)F_DIM * C_DIM / 2;
        #pragma unroll 8
        for (int k = 0; k < L_CHUNK; ++k) {
            float xv = xp[k * FT];
            u64 xx = pack2(xv, xv);
            u64 nur = fma2(Wr, ur, fma2(Wni, ui, xx));
            u64 nui = fma2(Wr, ui, mul2(Wi, ur));
            ur = nur;  ui = nui;
            float r0, r1, i0, i1;
            unpack2(ur, r0, r1);  unpack2(ui, i0, i1);
            *ow = make_float4(r0, i0, r1, i1);
            ow += stride4;
        }
    } else if (mode == 1) {                          // real part only
        float2* ow = (float2*)(out + bidx);
        const long long stride2 = (long long)F_DIM * C_DIM / 2;
        #pragma unroll 8
        for (int k = 0; k < L_CHUNK; ++k) {
            float xv = xp[k * FT];
            u64 xx = pack2(xv, xv);
            u64 nur = fma2(Wr, ur, fma2(Wni, ui, xx));
            u64 nui = fma2(Wr, ui, mul2(Wi, ur));
            ur = nur;  ui = nui;
            float r0, r1, i0, i1;
            unpack2(ur, r0, r1);  unpack2(ui, i0, i1);
            *ow = make_float2(r0, r1);
            ow += stride2;
        }
    } else {                                         // guarded interleaved
        float2* ob = (float2*)out;
        long long idx = bidx;
        const int stride = F_DIM * C_DIM;
        #pragma unroll 4
        for (int k = 0; k < L_CHUNK; ++k) {
            float xv = xp[k * FT];
            u64 xx = pack2(xv, xv);
            u64 nur = fma2(Wr, ur, fma2(Wni, ui, xx));
            u64 nui = fma2(Wr, ui, mul2(Wi, ur));
            ur = nur;  ui = nui;
            float r0, r1, i0, i1;
            unpack2(ur, r0, r1);  unpack2(ui, i0, i1);
            if (idx     < cap_f2) ob[idx]     = make_float2(r0, i0);
            if (idx + 1 < cap_f2) ob[idx + 1] = make_float2(r1, i1);
            idx += stride;
        }
    }
}

extern "C" void kernel_launch(void* const* d_in, const int* in_sizes, int n_in,
                              void* d_out, int out_size)
{
    const float* x     = nullptr;
    const float* mem_r = nullptr;
    const float* mem_i = nullptr;
    const float* a     = nullptr;
    const float* b     = nullptr;

    for (int i = 0; i < n_in; ++i) {
        switch (in_sizes[i]) {
            case B_DIM * T_DIM * F_DIM:
                x = (const float*)d_in[i]; break;
            case B_DIM * F_DIM * C_DIM:
                if (!mem_r) mem_r = (const float*)d_in[i];
                else        mem_i = (const float*)d_in[i];
                break;
            case F_DIM:
                a = (const float*)d_in[i]; break;
            case C_DIM:
                b = (const float*)d_in[i]; break;
            default: break;
        }
    }
    if (!x || !mem_r || !mem_i || !a || !b) {
        x     = (const float*)d_in[0];
        mem_r = (const float*)d_in[1];
        mem_i = (const float*)d_in[2];
        a     = (const float*)d_in[3];
        b     = (const float*)d_in[4];
    }

    int mode;
    long long cap_f2;
    if (out_size >= 2 * N_OUT)      { mode = 0; cap_f2 = N_OUT; }
    else if (out_size == N_OUT)     { mode = 1; cap_f2 = N_OUT; }
    else                            { mode = 2; cap_f2 = (long long)out_size / 2; }

    // 1024 blocks x 256 threads; warp = one f, lanes = (cpair, chunk).
    outer_laplace_ws<<<B_DIM * (F_DIM / FT), NTHR>>>(x, mem_r, mem_i, a, b,
                                                     (float*)d_out, mode, cap_f2);
}

// round 11
// speedup vs baseline: 2.0166x; 2.0166x over previous
#include <cuda_runtime.h>
#include <cuda_bf16.h>
#include <math.h>

// out[b,t,f,c] = sum_{s<=t} w^{t-s} x[b,s,f] + mem[b,f,c] * w^{t+1},
// w = exp(clip(a[f]) + i*b[c]) ==> complex IIR y[t] = w*y[t-1] + x[t], y[-1]=mem.
// 16 chunks of 32; E_i = w^32 E_{i-1} + S_i (exact Horner carry via smem).
// R8 mapping (warp = 2 chunks x 8 f x 2 cp -> coalesced stores) but NO smem
// x staging: phase 1 warms L1, phase 2 re-reads the same addresses (L1 hits).

#define B_DIM 8
#define T_DIM 512
#define F_DIM 1024
#define C_DIM 4
#define LIMIT_F 0.0766433975f                 // log(F32_MAX)/1024 - 0.01
#define N_OUT   (B_DIM * T_DIM * F_DIM * C_DIM)
#define L_CHUNK 32
#define N_CHUNK 16
#define FT      8                             // f-values per block
#define NTHR    256

typedef unsigned long long u64;

__device__ __forceinline__ u64 pack2(float lo, float hi) {
    u64 r; asm("mov.b64 %0, {%1, %2};" : "=l"(r) : "f"(lo), "f"(hi)); return r;
}
__device__ __forceinline__ void unpack2(u64 v, float& lo, float& hi) {
    asm("mov.b64 {%0, %1}, %2;" : "=f"(lo), "=f"(hi) : "l"(v));
}
__device__ __forceinline__ u64 fma2(u64 a, u64 b, u64 c) {
    u64 d; asm("fma.rn.f32x2 %0, %1, %2, %3;" : "=l"(d) : "l"(a), "l"(b), "l"(c)); return d;
}
__device__ __forceinline__ u64 mul2(u64 a, u64 b) {
    u64 d; asm("mul.rn.f32x2 %0, %1, %2;" : "=l"(d) : "l"(a), "l"(b)); return d;
}
__device__ __forceinline__ u64 neg2(u64 v) { return v ^ 0x8000000080000000ULL; }

__global__ __launch_bounds__(NTHR, 8)
void outer_laplace_ng(const float* __restrict__ x,
                      const float* __restrict__ mem_r,
                      const float* __restrict__ mem_i,
                      const float* __restrict__ a,
                      const float* __restrict__ b,
                      float* __restrict__ out,
                      int mode, long long cap_f2)
{
    __shared__ u64 SsmR[N_CHUNK][FT][2];             // 2 KB chunk sums (real)
    __shared__ u64 SsmI[N_CHUNK][FT][2];             // 2 KB (imag)

    const int tid   = threadIdx.x;
    const int cp    = tid & 1;                       // c{0,1} / c{2,3}
    const int f_idx = (tid >> 1) & (FT - 1);
    const int chunk = tid >> 4;                      // 0..15

    const int bb = blockIdx.x >> 7;                  // batch
    const int f0 = (blockIdx.x & 127) * FT;
    const int f  = f0 + f_idx;
    const int c0 = cp << 1;

    // ---- step coefficient w (packed over channel pair) ----
    const float ac = fminf(fmaxf(a[f], -LIMIT_F), -1e-8f);
    const float er = expf(ac);
    const float b0 = b[c0], b1 = b[c0 + 1];
    float s0, cz0, s1, cz1;
    sincosf(b0, &s0, &cz0);  sincosf(b1, &s1, &cz1);
    const u64 Wr  = pack2(er * cz0,  er * cz1);
    const u64 Wi  = pack2(er * s0,   er * s1);
    const u64 Wni = neg2(Wi);

    // x pointer for this thread's chunk: x[b, chunk*32 + k, f]
    const float* xp = x + ((size_t)bb * T_DIM + chunk * L_CHUNK) * F_DIM + f;

    // ---- phase 1: chunk-local scan from zero (reads gmem, warms L1) ----
    u64 ur = 0ull, ui = 0ull;
    #pragma unroll 8
    for (int k = 0; k < L_CHUNK; ++k) {
        float xv = __ldg(xp + (size_t)k * F_DIM);
        u64 xx = pack2(xv, xv);
        u64 nur = fma2(Wr, ur, fma2(Wni, ui, xx));
        u64 nui = fma2(Wr, ui, mul2(Wi, ur));
        ur = nur;  ui = nui;
    }
    SsmR[chunk][f_idx][cp] = ur;
    SsmI[chunk][f_idx][cp] = ui;
    __syncthreads();                                 // the ONLY barrier

    // ---- carry: Horner over previous chunk sums, seeded by memory ----
    {
        const float erL = expf(ac * (float)L_CHUNK);
        float sL0, cL0, sL1, cL1;
        sincosf(b0 * (float)L_CHUNK, &sL0, &cL0);
        sincosf(b1 * (float)L_CHUNK, &sL1, &cL1);
        const u64 WLr  = pack2(erL * cL0,  erL * cL1);
        const u64 WLi  = pack2(erL * sL0,  erL * sL1);
        const u64 WLni = neg2(WLi);

        const int mbase = (((bb << 10) + f) << 2) + c0;
        u64 cr = pack2(mem_r[mbase], mem_r[mbase + 1]);
        u64 ci = pack2(mem_i[mbase], mem_i[mbase + 1]);
        for (int j = 0; j < chunk; ++j) {            // <=15 iters
            u64 Sr = SsmR[j][f_idx][cp];
            u64 Si = SsmI[j][f_idx][cp];
            u64 ncr = fma2(WLr, cr, fma2(WLni, ci, Sr));
            u64 nci = fma2(WLr, ci, fma2(WLi, cr, Si));
            cr = ncr;  ci = nci;
        }
        ur = cr;  ui = ci;
    }

    // ---- phase 2: re-scan with correct init (x now L1-hot), vector stores ----
    long long bidx = ((long long)bb * T_DIM + chunk * L_CHUNK) * (F_DIM * C_DIM)
                   + (f << 2) + c0;                  // complex-element index

    if (mode == 0) {                                 // interleaved complex64
        float4* ow = (float4*)((float2*)out + bidx);
        const long long stride4 = (long long)F_DIM * C_DIM / 2;
        #pragma unroll 8
        for (int k = 0; k < L_CHUNK; ++k) {
            float xv = __ldg(xp + (size_t)k * F_DIM);
            u64 xx = pack2(xv, xv);
            u64 nur = fma2(Wr, ur, fma2(Wni, ui, xx));
            u64 nui = fma2(Wr, ui, mul2(Wi, ur));
            ur = nur;  ui = nui;
            float r0, r1, i0, i1;
            unpack2(ur, r0, r1);  unpack2(ui, i0, i1);
            *ow = make_float4(r0, i0, r1, i1);
            ow += stride4;
        }
    } else if (mode == 1) {                          // real part only
        float2* ow = (float2*)(out + bidx);
        const long long stride2 = (long long)F_DIM * C_DIM / 2;
        #pragma unroll 8
        for (int k = 0; k < L_CHUNK; ++k) {
            float xv = __ldg(xp + (size_t)k * F_DIM);
            u64 xx = pack2(xv, xv);
            u64 nur = fma2(Wr, ur, fma2(Wni, ui, xx));
            u64 nui = fma2(Wr, ui, mul2(Wi, ur));
            ur = nur;  ui = nui;
            float r0, r1, i0, i1;
            unpack2(ur, r0, r1);  unpack2(ui, i0, i1);
            *ow = make_float2(r0, r1);
            ow += stride2;
        }
    } else {                                         // guarded interleaved
        float2* ob = (float2*)out;
        long long idx = bidx;
        const int stride = F_DIM * C_DIM;
        #pragma unroll 4
        for (int k = 0; k < L_CHUNK; ++k) {
            float xv = __ldg(xp + (size_t)k * F_DIM);
            u64 xx = pack2(xv, xv);
            u64 nur = fma2(Wr, ur, fma2(Wni, ui, xx));
            u64 nui = fma2(Wr, ui, mul2(Wi, ur));
            ur = nur;  ui = nui;
            float r0, r1, i0, i1;
            unpack2(ur, r0, r1);  unpack2(ui, i0, i1);
            if (idx     < cap_f2) ob[idx]     = make_float2(r0, i0);
            if (idx + 1 < cap_f2) ob[idx + 1] = make_float2(r1, i1);
            idx += stride;
        }
    }
}

extern "C" void kernel_launch(void* const* d_in, const int* in_sizes, int n_in,
                              void* d_out, int out_size)
{
    const float* x     = nullptr;
    const float* mem_r = nullptr;
    const float* mem_i = nullptr;
    const float* a     = nullptr;
    const float* b     = nullptr;

    for (int i = 0; i < n_in; ++i) {
        switch (in_sizes[i]) {
            case B_DIM * T_DIM * F_DIM:
                x = (const float*)d_in[i]; break;
            case B_DIM * F_DIM * C_DIM:
                if (!mem_r) mem_r = (const float*)d_in[i];
                else        mem_i = (const float*)d_in[i];
                break;
            case F_DIM:
                a = (const float*)d_in[i]; break;
            case C_DIM:
                b = (const float*)d_in[i]; break;
            default: break;
        }
    }
    if (!x || !mem_r || !mem_i || !a || !b) {
        x     = (const float*)d_in[0];
        mem_r = (const float*)d_in[1];
        mem_i = (const float*)d_in[2];
        a     = (const float*)d_in[3];
        b     = (const float*)d_in[4];
    }

    int mode;
    long long cap_f2;
    if (out_size >= 2 * N_OUT)      { mode = 0; cap_f2 = N_OUT; }
    else if (out_size == N_OUT)     { mode = 1; cap_f2 = N_OUT; }
    else                            { mode = 2; cap_f2 = (long long)out_size / 2; }

    // 1024 blocks x 256 threads; no x staging, 4 KB smem, 8 blocks/SM.
    outer_laplace_ng<<<B_DIM * (F_DIM / FT), NTHR>>>(x, mem_r, mem_i, a, b,
                                                     (float*)d_out, mode, cap_f2);
}

// round 12
// speedup vs baseline: 2.3086x; 1.1448x over previous
#include <cuda_runtime.h>
#include <cuda_bf16.h>
#include <math.h>

// out[b,t,f,c] = sum_{s<=t} w^{t-s} x[b,s,f] + mem[b,f,c] * w^{t+1},
// w = exp(clip(a[f]) + i*b[c]) ==> complex IIR y[t] = w*y[t-1] + x[t], y[-1]=mem.
// 16 chunks of 32; E_i = w^32 E_{i-1} + S_i (exact Horner carry via smem).
// x staged TRANSPOSED (xs[f][t], stride 516) -> per-chunk x is contiguous,
// loaded as LDS.128 (8 per phase instead of 32 scalar LDS). FFMA2-packed math.

#define B_DIM 8
#define T_DIM 512
#define F_DIM 1024
#define C_DIM 4
#define LIMIT_F 0.0766433975f                 // log(F32_MAX)/1024 - 0.01
#define N_OUT   (B_DIM * T_DIM * F_DIM * C_DIM)
#define L_CHUNK 32
#define N_CHUNK 16
#define FT      8                             // f-values per block
#define NTHR    256
#define XSTRIDE 516                           // floats per f-row (bank-spread pad)

typedef unsigned long long u64;

__device__ __forceinline__ u64 pack2(float lo, float hi) {
    u64 r; asm("mov.b64 %0, {%1, %2};" : "=l"(r) : "f"(lo), "f"(hi)); return r;
}
__device__ __forceinline__ void unpack2(u64 v, float& lo, float& hi) {
    asm("mov.b64 {%0, %1}, %2;" : "=f"(lo), "=f"(hi) : "l"(v));
}
__device__ __forceinline__ u64 fma2(u64 a, u64 b, u64 c) {
    u64 d; asm("fma.rn.f32x2 %0, %1, %2, %3;" : "=l"(d) : "l"(a), "l"(b), "l"(c)); return d;
}
__device__ __forceinline__ u64 mul2(u64 a, u64 b) {
    u64 d; asm("mul.rn.f32x2 %0, %1, %2;" : "=l"(d) : "l"(a), "l"(b)); return d;
}
__device__ __forceinline__ u64 neg2(u64 v) { return v ^ 0x8000000080000000ULL; }

// one packed complex IIR step on 2 channels
#define STEP(xv)                                              \
    do {                                                      \
        u64 xx  = pack2((xv), (xv));                          \
        u64 nur = fma2(Wr, ur, fma2(Wni, ui, xx));            \
        u64 nui = fma2(Wr, ui, mul2(Wi, ur));                 \
        ur = nur;  ui = nui;                                  \
    } while (0)

__global__ __launch_bounds__(NTHR, 7)
void outer_laplace_tx(const float* __restrict__ x,
                      const float* __restrict__ mem_r,
                      const float* __restrict__ mem_i,
                      const float* __restrict__ a,
                      const float* __restrict__ b,
                      float* __restrict__ out,
                      int mode, long long cap_f2)
{
    __shared__ float xs[FT * XSTRIDE];               // 16.1 KB, xs[f*516 + t]
    __shared__ u64 SsmR[N_CHUNK][FT][2];             // 2 KB chunk sums (real)
    __shared__ u64 SsmI[N_CHUNK][FT][2];             // 2 KB (imag)

    const int tid   = threadIdx.x;
    const int cp    = tid & 1;                       // c{0,1} / c{2,3}
    const int f_idx = (tid >> 1) & (FT - 1);
    const int chunk = tid >> 4;                      // 0..15

    const int bb = blockIdx.x >> 7;                  // batch
    const int f0 = (blockIdx.x & 127) * FT;
    const int f  = f0 + f_idx;
    const int c0 = cp << 1;

    // ---- stage x[b, :, f0:f0+8] transposed: xs[f][t] ----
    // lane i covers (t = i>>3, f = i&7): LDG coalesced (4x32B sectors/warp),
    // STS banks = 4f + (t&3) -> 32 distinct, conflict-free.
    {
        const float* xg = x + (size_t)bb * T_DIM * F_DIM + f0;
        #pragma unroll 16
        for (int i = tid; i < T_DIM * FT; i += NTHR) {
            int t = i >> 3, ff = i & 7;
            xs[ff * XSTRIDE + t] = __ldg(xg + (size_t)t * F_DIM + ff);
        }
    }

    // ---- step coefficient w (packed over channel pair) ----
    const float ac = fminf(fmaxf(a[f], -LIMIT_F), -1e-8f);
    const float er = expf(ac);
    const float b0 = b[c0], b1 = b[c0 + 1];
    float s0, cz0, s1, cz1;
    sincosf(b0, &s0, &cz0);  sincosf(b1, &s1, &cz1);
    const u64 Wr  = pack2(er * cz0,  er * cz1);
    const u64 Wi  = pack2(er * s0,   er * s1);
    const u64 Wni = neg2(Wi);

    __syncthreads();

    // this thread's chunk x: 32 contiguous floats (16B-aligned: chunk*32)
    const float4* xq = (const float4*)&xs[f_idx * XSTRIDE + chunk * L_CHUNK];

    // ---- phase 1: chunk-local scan from zero (LDS.128 x8) ----
    u64 ur = 0ull, ui = 0ull;
    #pragma unroll
    for (int j = 0; j < L_CHUNK / 4; ++j) {
        float4 v = xq[j];
        STEP(v.x); STEP(v.y); STEP(v.z); STEP(v.w);
    }
    SsmR[chunk][f_idx][cp] = ur;
    SsmI[chunk][f_idx][cp] = ui;
    __syncthreads();

    // ---- carry: Horner over previous chunk sums, seeded by memory ----
    {
        const float erL = expf(ac * (float)L_CHUNK);
        float sL0, cL0, sL1, cL1;
        sincosf(b0 * (float)L_CHUNK, &sL0, &cL0);
        sincosf(b1 * (float)L_CHUNK, &sL1, &cL1);
        const u64 WLr  = pack2(erL * cL0,  erL * cL1);
        const u64 WLi  = pack2(erL * sL0,  erL * sL1);
        const u64 WLni = neg2(WLi);

        const int mbase = (((bb << 10) + f) << 2) + c0;
        u64 cr = pack2(mem_r[mbase], mem_r[mbase + 1]);
        u64 ci = pack2(mem_i[mbase], mem_i[mbase + 1]);
        for (int j = 0; j < chunk; ++j) {            // <=15 iters
            u64 Sr = SsmR[j][f_idx][cp];
            u64 Si = SsmI[j][f_idx][cp];
            u64 ncr = fma2(WLr, cr, fma2(WLni, ci, Sr));
            u64 nci = fma2(WLr, ci, fma2(WLi, cr, Si));
            cr = ncr;  ci = nci;
        }
        ur = cr;  ui = ci;
    }

    // ---- phase 2: re-scan with correct init, STG.128 stores ----
    long long bidx = ((long long)bb * T_DIM + chunk * L_CHUNK) * (F_DIM * C_DIM)
                   + (f << 2) + c0;                  // complex-element index

    if (mode == 0) {                                 // interleaved complex64
        float4* ow = (float4*)((float2*)out + bidx);
        const long long stride4 = (long long)F_DIM * C_DIM / 2;
        #pragma unroll
        for (int j = 0; j < L_CHUNK / 4; ++j) {
            float4 v = xq[j];
            float r0, r1, i0, i1;
            STEP(v.x);
            unpack2(ur, r0, r1);  unpack2(ui, i0, i1);
            ow[0] = make_float4(r0, i0, r1, i1);
            STEP(v.y);
            unpack2(ur, r0, r1);  unpack2(ui, i0, i1);
            ow[stride4] = make_float4(r0, i0, r1, i1);
            STEP(v.z);
            unpack2(ur, r0, r1);  unpack2(ui, i0, i1);
            ow[2 * stride4] = make_float4(r0, i0, r1, i1);
            STEP(v.w);
            unpack2(ur, r0, r1);  unpack2(ui, i0, i1);
            ow[3 * stride4] = make_float4(r0, i0, r1, i1);
            ow += 4 * stride4;
        }
    } else if (mode == 1) {                          // real part only
        float2* ow = (float2*)(out + bidx);
        const long long stride2 = (long long)F_DIM * C_DIM / 2;
        #pragma unroll
        for (int j = 0; j < L_CHUNK / 4; ++j) {
            float4 v = xq[j];
            float r0, r1, i0, i1;
            STEP(v.x);
            unpack2(ur, r0, r1);  unpack2(ui, i0, i1);
            ow[0] = make_float2(r0, r1);
            STEP(v.y);
            unpack2(ur, r0, r1);  unpack2(ui, i0, i1);
            ow[stride2] = make_float2(r0, r1);
            STEP(v.z);
            unpack2(ur, r0, r1);  unpack2(ui, i0, i1);
            ow[2 * stride2] = make_float2(r0, r1);
            STEP(v.w);
            unpack2(ur, r0, r1);  unpack2(ui, i0, i1);
            ow[3 * stride2] = make_float2(r0, r1);
            ow += 4 * stride2;
        }
    } else {                                         // guarded interleaved
        float2* ob = (float2*)out;
        long long idx = bidx;
        const int stride = F_DIM * C_DIM;
        const float* xs1 = (const float*)xq;
        #pragma unroll 4
        for (int k = 0; k < L_CHUNK; ++k) {
            float xv = xs1[k];
            STEP(xv);
            float r0, r1, i0, i1;
            unpack2(ur, r0, r1);  unpack2(ui, i0, i1);
            if (idx     < cap_f2) ob[idx]     = make_float2(r0, i0);
            if (idx + 1 < cap_f2) ob[idx + 1] = make_float2(r1, i1);
            idx += stride;
        }
    }
}

extern "C" void kernel_launch(void* const* d_in, const int* in_sizes, int n_in,
                              void* d_out, int out_size)
{
    const float* x     = nullptr;
    const float* mem_r = nullptr;
    const float* mem_i = nullptr;
    const float* a     = nullptr;
    const float* b     = nullptr;

    for (int i = 0; i < n_in; ++i) {
        switch (in_sizes[i]) {
            case B_DIM * T_DIM * F_DIM:
                x = (const float*)d_in[i]; break;
            case B_DIM * F_DIM * C_DIM:
                if (!mem_r) mem_r = (const float*)d_in[i];
                else        mem_i = (const float*)d_in[i];
                break;
            case F_DIM:
                a = (const float*)d_in[i]; break;
            case C_DIM:
                b = (const float*)d_in[i]; break;
            default: break;
        }
    }
    if (!x || !mem_r || !mem_i || !a || !b) {
        x     = (const float*)d_in[0];
        mem_r = (const float*)d_in[1];
        mem_i = (const float*)d_in[2];
        a     = (const float*)d_in[3];
        b     = (const float*)d_in[4];
    }

    int mode;
    long long cap_f2;
    if (out_size >= 2 * N_OUT)      { mode = 0; cap_f2 = N_OUT; }
    else if (out_size == N_OUT)     { mode = 1; cap_f2 = N_OUT; }
    else                            { mode = 2; cap_f2 = (long long)out_size / 2; }

    // 1024 blocks x 256 threads; transposed staging, LDS.128 phase loads.
    outer_laplace_tx<<<B_DIM * (F_DIM / FT), NTHR>>>(x, mem_r, mem_i, a, b,
                                                     (float*)d_out, mode, cap_f2);
}

// round 13
// speedup vs baseline: 2.5360x; 1.0985x over previous
#include <cuda_runtime.h>
#include <cuda_bf16.h>
#include <math.h>

// out[b,t,f,c] = sum_{s<=t} w^{t-s} x[b,s,f] + mem[b,f,c] * w^{t+1},
// w = exp(clip(a[f]) + i*b[c])  ==> complex IIR  y[t] = w*y[t-1] + x[t], y[-1]=mem.
// Parallel-in-T: 8 chunks of 64; chunk sums compose via E_i = w^64 E_{i-1} + S_i.
// R4 structure (best measured: ncu 17.6us) + streaming cache hints:
//   __ldcs on x staging (read-once), __stcs on output (write-streaming, 134MB
//   cycles the whole 126MB L2 every launch -> evict-first reduces thrash).

#define B_DIM 8
#define T_DIM 512
#define F_DIM 1024
#define C_DIM 4
#define LIMIT_F 0.0766433975f                 // log(F32_MAX)/1024 - 0.01
#define N_OUT   (B_DIM * T_DIM * F_DIM * C_DIM)
#define L_CHUNK 64
#define N_CHUNK 8

__global__ __launch_bounds__(256, 6)
void outer_laplace_scan(const float* __restrict__ x,
                        const float* __restrict__ mem_r,
                        const float* __restrict__ mem_i,
                        const float* __restrict__ a,
                        const float* __restrict__ b,
                        float* __restrict__ out,
                        int mode, long long cap_f2)
{
    __shared__ float  xs[T_DIM * 8];          // x[b, :, f0:f0+8]  (16 KB)
    __shared__ float2 Ssm[N_CHUNK][32];       // chunk-local end sums (2 KB)

    const int tid   = threadIdx.x;
    const int lane  = tid & 31;               // (f_off, c) pair
    const int chunk = tid >> 5;               // warp id = chunk id

    const int bb    = blockIdx.x >> 7;        // batch
    const int f0    = (blockIdx.x & 127) << 3;
    const int f_off = lane >> 2;
    const int c     = lane & 3;
    const int f     = f0 + f_off;

    // ---- phase 0: stage x slice into smem (read-once -> evict-first) ----
    const float4* xg = (const float4*)(x + (size_t)bb * T_DIM * F_DIM + f0);
    #pragma unroll 4
    for (int idx = tid; idx < T_DIM * 2; idx += 256) {
        int t = idx >> 1, half = idx & 1;
        *(float4*)&xs[t * 8 + half * 4] = __ldcs(&xg[(size_t)t * (F_DIM / 4) + half]);
    }

    // ---- coefficients: w and w^64 (exact) ----
    float ac = fminf(fmaxf(a[f], -LIMIT_F), -1e-8f);
    float bc = b[c];
    float er = expf(ac);
    float sn, cs; sincosf(bc, &sn, &cs);
    const float wr = er * cs, wi = er * sn;

    float erL = expf(ac * (float)L_CHUNK);
    float snL, csL; sincosf(bc * (float)L_CHUNK, &snL, &csL);
    const float wLr = erL * csL, wLi = erL * snL;

    __syncthreads();

    // ---- phase 1: chunk-local scan from zero ----
    {
        float yr = 0.f, yi = 0.f;
        const float* xp = &xs[chunk * L_CHUNK * 8 + f_off];
        #pragma unroll 16
        for (int k = 0; k < L_CHUNK; ++k) {
            float xv  = xp[k * 8];
            float nyr = fmaf(wr, yr, fmaf(-wi, yi, xv));
            float nyi = fmaf(wr, yi, wi * yr);
            yr = nyr; yi = nyi;
        }
        Ssm[chunk][lane] = make_float2(yr, yi);
    }
    __syncthreads();

    // ---- carry: E_{chunk-1} = Horner over previous chunk sums, seeded by mem ----
    const int midx = (bb << 12) + (f << 2) + c;
    float cr = mem_r[midx], ci = mem_i[midx];
    for (int j = 0; j < chunk; ++j) {         // uniform per warp, <=7 iters
        float2 S = Ssm[j][lane];
        float nr = fmaf(wLr, cr, fmaf(-wLi, ci, S.x));
        float ni = fmaf(wLr, ci, fmaf(wLi, cr, S.y));
        cr = nr; ci = ni;
    }

    // ---- phase 2: re-scan with correct init, streaming stores ----
    float yr = cr, yi = ci;
    const float* xp = &xs[chunk * L_CHUNK * 8 + f_off];
    long long idx = ((long long)bb * T_DIM + chunk * L_CHUNK) * (F_DIM * C_DIM)
                  + (f << 2) + c;
    const int stride = F_DIM * C_DIM;

    if (mode == 0) {
        float2* ob = (float2*)out;
        #pragma unroll 16
        for (int k = 0; k < L_CHUNK; ++k) {
            float xv  = xp[k * 8];
            float nyr = fmaf(wr, yr, fmaf(-wi, yi, xv));
            float nyi = fmaf(wr, yi, wi * yr);
            yr = nyr; yi = nyi;
            __stcs(&ob[idx], make_float2(yr, yi));
            idx += stride;
        }
    } else if (mode == 1) {
        #pragma unroll 16
        for (int k = 0; k < L_CHUNK; ++k) {
            float xv  = xp[k * 8];
            float nyr = fmaf(wr, yr, fmaf(-wi, yi, xv));
            float nyi = fmaf(wr, yi, wi * yr);
            yr = nyr; yi = nyi;
            __stcs(&out[idx], yr);
            idx += stride;
        }
    } else {
        float2* ob = (float2*)out;
        #pragma unroll 8
        for (int k = 0; k < L_CHUNK; ++k) {
            float xv  = xp[k * 8];
            float nyr = fmaf(wr, yr, fmaf(-wi, yi, xv));
            float nyi = fmaf(wr, yi, wi * yr);
            yr = nyr; yi = nyi;
            if (idx < cap_f2) __stcs(&ob[idx], make_float2(yr, yi));
            idx += stride;
        }
    }
}

extern "C" void kernel_launch(void* const* d_in, const int* in_sizes, int n_in,
                              void* d_out, int out_size)
{
    const float* x     = nullptr;
    const float* mem_r = nullptr;
    const float* mem_i = nullptr;
    const float* a     = nullptr;
    const float* b     = nullptr;

    for (int i = 0; i < n_in; ++i) {
        switch (in_sizes[i]) {
            case B_DIM * T_DIM * F_DIM:
                x = (const float*)d_in[i]; break;
            case B_DIM * F_DIM * C_DIM:
                if (!mem_r) mem_r = (const float*)d_in[i];
                else        mem_i = (const float*)d_in[i];
                break;
            case F_DIM:
                a = (const float*)d_in[i]; break;
            case C_DIM:
                b = (const float*)d_in[i]; break;
            default: break;
        }
    }
    if (!x || !mem_r || !mem_i || !a || !b) {
        x     = (const float*)d_in[0];
        mem_r = (const float*)d_in[1];
        mem_i = (const float*)d_in[2];
        a     = (const float*)d_in[3];
        b     = (const float*)d_in[4];
    }

    int mode;
    long long cap_f2;
    if (out_size >= 2 * N_OUT)      { mode = 0; cap_f2 = N_OUT; }
    else if (out_size == N_OUT)     { mode = 1; cap_f2 = N_OUT; }
    else                            { mode = 2; cap_f2 = (long long)out_size / 2; }

    // 1024 blocks x 256 threads: block = (batch, 8 f-values), warps = chunks.
    outer_laplace_scan<<<1024, 256>>>(x, mem_r, mem_i, a, b,
                                      (float*)d_out, mode, cap_f2);
}